// round 7
// baseline (speedup 1.0000x reference)
#include <cuda_runtime.h>
#include <math.h>

#define T_STEPS 512
#define BATCH   128
#define DIM     512
#define HID     512

#define NB   128      // 4 batch-groups x 32 col-groups
#define STPB 256
#define WS   516      // padded smem row stride
#define REDL 33       // reduction stride (32 batches + pad)

// cross-block sync state (self-resetting at kernel end for graph replay)
__device__ volatile unsigned g_flagv[NB];
__device__ unsigned g_cA[4];
__device__ unsigned g_cB[4];

__device__ __forceinline__ void ffma2(unsigned long long& d,
                                      unsigned long long a,
                                      unsigned long long b) {
    asm("fma.rn.f32x2 %0, %1, %2, %0;" : "+l"(d) : "l"(a), "l"(b));
}
__device__ __forceinline__ void unpack2(unsigned long long v, float& lo, float& hi) {
    asm("mov.b64 {%0, %1}, %2;" : "=f"(lo), "=f"(hi) : "l"(v));
}

// [32b x 128k] x [128k x 48cols] fragment: 2 batch rows from GLOBAL, W from smem.
// wb = weight smem base + cgrp*WS + k0. acc[bi][ci][g].
__device__ __forceinline__ void gemm_k128(
    const float* __restrict__ s0, const float* __restrict__ s1,
    const float* __restrict__ wb,
    unsigned long long acc[2][4][3])
{
#pragma unroll 4
    for (int kk = 0; kk < 128; kk += 4) {
        ulonglong2 a0 = *(const ulonglong2*)(s0 + kk);
        ulonglong2 a1 = *(const ulonglong2*)(s1 + kk);
#pragma unroll
        for (int g = 0; g < 3; g++)
#pragma unroll
            for (int ci = 0; ci < 4; ci++) {
                ulonglong2 w = *(const ulonglong2*)(wb + (g * 16 + 4 * ci) * WS + kk);
                ffma2(acc[0][ci][g], a0.x, w.x); ffma2(acc[0][ci][g], a0.y, w.y);
                ffma2(acc[1][ci][g], a1.x, w.x); ffma2(acc[1][ci][g], a1.y, w.y);
            }
    }
}

// ---------------------------------------------------------------------------
// Fused GRU: per step, x-GEMM (no barrier dep) -> flag barrier -> h-GEMM ->
// gates. Grid: 4 batch-groups (bg, 32 batches) x 32 col-groups (cg, 16 cols).
// Block 256 thr = 8 warps: ks = wid&3 (k-slice of 128), bhf = wid>>2 (batch
// half of 16). Lane: bgrp = lane>>2, cgrp = lane&3.
// Thread GEMM tile: batches {bhf*16+bgrp+8bi}, cols {cgrp+4ci}, 3 gates.
// Gate phase: thread -> col co=tid>>4, batches {2*(tid&15), +1}.
// ---------------------------------------------------------------------------
__global__ __launch_bounds__(STPB, 1) void gru_fused_kernel(
    const float* __restrict__ inputs,
    const float* __restrict__ Wih,
    const float* __restrict__ Whh,
    const float* __restrict__ bih,
    const float* __restrict__ bhh,
    float* __restrict__ out)
{
    extern __shared__ float smem[];
    float* wih_s = smem;                   // 48 x WS
    float* whh_s = smem + 48 * WS;         // 48 x WS
    float* red   = smem + 96 * WS;         // [3][16][4][REDL]

    const int tid  = threadIdx.x;
    const int bk   = blockIdx.x;
    const int bg   = bk >> 5;
    const int cg   = bk & 31;
    const int wid  = tid >> 5;
    const int lane = tid & 31;
    const int ks   = wid & 3;              // k-slice
    const int bhf  = wid >> 2;             // batch half
    const int bgrp = lane >> 2;
    const int cgrp = lane & 3;
    const int k0   = ks * 128;

    // load both weight slices: smem row (g*16+lc) <- W row (g*512 + cg*16 + lc)
    for (int i = tid; i < 48 * 128; i += STPB) {
        int row = i >> 7, q = i & 127;
        int g = row >> 4, lc = row & 15;
        size_t gro = (size_t)(g * 512 + cg * 16 + lc) * 512 + q * 4;
        *(float4*)&wih_s[row * WS + q * 4] = *(const float4*)(Wih + gro);
        *(float4*)&whh_s[row * WS + q * 4] = *(const float4*)(Whh + gro);
    }

    // gate-phase mapping
    const int co  = tid >> 4;
    const int bo  = (tid & 15) * 2;
    const int cGo = cg * 16 + co;
    const int bGo = bg * 32 + bo;
    const float br   = bih[cGo] + bhh[cGo];
    const float bz   = bih[512 + cGo] + bhh[512 + cGo];
    const float bin_ = bih[1024 + cGo];
    const float bhn  = bhh[1024 + cGo];
    __syncthreads();

    float hprev[2] = {0.f, 0.f};

    // GEMM-phase row indices and publish base
    const int rL0 = bhf * 16 + bgrp;       // local rows rL0, rL0+8
    const int rG0 = bg * 32 + rL0;
    float* rpub = red + ks * REDL + rL0;   // + (g*16+cgrp+4ci)*4*REDL + 8*bi

    for (int t = 0; t < T_STEPS; t++) {
        unsigned long long acc[2][4][3];

        // ---- x-phase: x[t] @ W_ih^T (no barrier dependency) ----
#pragma unroll
        for (int bi = 0; bi < 2; bi++)
#pragma unroll
            for (int ci = 0; ci < 4; ci++)
#pragma unroll
                for (int g = 0; g < 3; g++) acc[bi][ci][g] = 0ULL;
        {
            const float* xb = inputs + ((size_t)t * BATCH + rG0) * DIM + k0;
            gemm_k128(xb, xb + 8 * DIM, wih_s + cgrp * WS + k0, acc);
        }
#pragma unroll
        for (int bi = 0; bi < 2; bi++)
#pragma unroll
            for (int ci = 0; ci < 4; ci++)
#pragma unroll
                for (int g = 0; g < 3; g++) {
                    float lo, hi;
                    unpack2(acc[bi][ci][g], lo, hi);
                    rpub[(g * 16 + cgrp + 4 * ci) * 4 * REDL + 8 * bi] = lo + hi;
                }
        __syncthreads();

        // fold x-partials into registers; warp 0 polls peer flags meanwhile
        float xg[2][3];
#pragma unroll
        for (int j = 0; j < 2; j++)
#pragma unroll
            for (int g = 0; g < 3; g++) {
                float s = 0.f;
#pragma unroll
                for (int k4 = 0; k4 < 4; k4++)
                    s += red[((g * 16 + co) * 4 + k4) * REDL + bo + j];
                xg[j][g] = s;
            }
        if (t > 0 && tid < 32) {
            volatile unsigned* f = &g_flagv[bg * 32 + tid];
            while (*f < (unsigned)t) { }
        }
        __threadfence();
        __syncthreads();   // x-partials consumed; h[t-1] visible

        // ---- h-phase: h[t-1] @ W_hh^T ----
        if (t > 0) {
            // prefetch next step's x slice into L2 (512 lines of 128B)
            if (t + 1 < T_STEPS) {
                const float* nx = inputs + ((size_t)(t + 1) * BATCH + bg * 32) * DIM;
                asm volatile("prefetch.global.L2 [%0];" :: "l"(nx + tid * 64));
                asm volatile("prefetch.global.L2 [%0];" :: "l"(nx + tid * 64 + 32));
            }
#pragma unroll
            for (int bi = 0; bi < 2; bi++)
#pragma unroll
                for (int ci = 0; ci < 4; ci++)
#pragma unroll
                    for (int g = 0; g < 3; g++) acc[bi][ci][g] = 0ULL;
            const float* hb = out + ((size_t)(t - 1) * BATCH + rG0) * HID + k0;
            gemm_k128(hb, hb + 8 * HID, whh_s + cgrp * WS + k0, acc);
#pragma unroll
            for (int bi = 0; bi < 2; bi++)
#pragma unroll
                for (int ci = 0; ci < 4; ci++)
#pragma unroll
                    for (int g = 0; g < 3; g++) {
                        float lo, hi;
                        unpack2(acc[bi][ci][g], lo, hi);
                        rpub[(g * 16 + cgrp + 4 * ci) * 4 * REDL + 8 * bi] = lo + hi;
                    }
            __syncthreads();
        }

        // ---- gates ----
        {
            float* ob = out + (size_t)t * (BATCH * HID);
#pragma unroll
            for (int j = 0; j < 2; j++) {
                float s[3] = {0.f, 0.f, 0.f};
                if (t > 0) {
#pragma unroll
                    for (int g = 0; g < 3; g++) {
                        float a = 0.f;
#pragma unroll
                        for (int k4 = 0; k4 < 4; k4++)
                            a += red[((g * 16 + co) * 4 + k4) * REDL + bo + j];
                        s[g] = a;
                    }
                }
                float r = 1.f / (1.f + __expf(-(xg[j][0] + s[0] + br)));
                float z = 1.f / (1.f + __expf(-(xg[j][1] + s[1] + bz)));
                float n = tanhf(xg[j][2] + bin_ + r * (s[2] + bhn));
                float hv = (1.f - z) * n + z * hprev[j];
                hprev[j] = hv;
                ob[(size_t)(bGo + j) * HID + cGo] = hv;
            }
        }

        // ---- signal h[t] complete ----
        if (t < T_STEPS - 1) {
            __threadfence();
            __syncthreads();
            if (tid == 0) g_flagv[bk] = (unsigned)(t + 1);
        }
    }

    // ---- cleanup: reset flags/counters for next graph replay ----
    __syncthreads();
    if (tid == 0) {
        atomicAdd(&g_cA[bg], 1u);
        while (((volatile unsigned*)g_cA)[bg] < 32u) { }
        g_flagv[bk] = 0u;              // safe: all blocks past all polls
        __threadfence();
        unsigned q = atomicAdd(&g_cB[bg], 1u);
        if (q == 31u) {                // last block: nobody polls counters now
            g_cA[bg] = 0u;
            g_cB[bg] = 0u;
            __threadfence();
        }
    }
}

// ---------------------------------------------------------------------------
extern "C" void kernel_launch(void* const* d_in, const int* in_sizes, int n_in,
                              void* d_out, int out_size)
{
    const float* inputs = (const float*)d_in[0];   // [T,B,D]
    const float* W_ih   = (const float*)d_in[1];   // [3H,D]
    const float* W_hh   = (const float*)d_in[2];   // [3H,H]
    const float* b_ih   = (const float*)d_in[3];
    const float* b_hh   = (const float*)d_in[4];
    float* out = (float*)d_out;                    // [T,B,H]

    (void)in_sizes; (void)n_in; (void)out_size;

    const int dyn_smem = (96 * WS + 3 * 16 * 4 * REDL) * (int)sizeof(float); // 223.5 KB
    static int smem_set = 0;
    if (!smem_set) {
        cudaFuncSetAttribute(gru_fused_kernel,
                             cudaFuncAttributeMaxDynamicSharedMemorySize, dyn_smem);
        smem_set = 1;
    }

    gru_fused_kernel<<<NB, STPB, dyn_smem>>>(inputs, W_ih, W_hh, b_ih, b_hh, out);
}

// round 8
// speedup vs baseline: 1.2145x; 1.2145x over previous
#include <cuda_runtime.h>
#include <math.h>

#define T_STEPS 512
#define BATCH   128
#define DIM     512
#define HID     512
#define G3      1536

#define NB   128      // scan blocks: 4 batch-groups x 32 col-groups
#define STPB 256
#define WS   516      // padded smem row stride (floats)
#define REDL 33       // reduction inner stride

__device__ float g_xp[(size_t)T_STEPS * BATCH * G3];
// flag barrier state (self-resetting for graph replay)
__device__ volatile unsigned g_flagv[NB];
__device__ unsigned g_cA[4];
__device__ unsigned g_cB[4];

__device__ __forceinline__ void ffma2(unsigned long long& d,
                                      unsigned long long a,
                                      unsigned long long b) {
    asm("fma.rn.f32x2 %0, %1, %2, %0;" : "+l"(d) : "l"(a), "l"(b));
}
__device__ __forceinline__ unsigned long long splat2(float a) {
    unsigned long long d;
    asm("mov.b64 %0, {%1, %1};" : "=l"(d) : "f"(a));
    return d;
}
__device__ __forceinline__ void unpack2(unsigned long long v, float& lo, float& hi) {
    asm("mov.b64 {%0, %1}, %2;" : "=f"(lo), "=f"(hi) : "l"(v));
}
__device__ __forceinline__ void cpasync16(unsigned int saddr, const void* gaddr) {
    asm volatile("cp.async.cg.shared.global [%0], [%1], 16;"
                 :: "r"(saddr), "l"(gaddr));
}

// ---------------------------------------------------------------------------
// Kernel 1: x_proj = X @ W_ih^T + b_ih   (M=65536, K=512, N=1536)
// ---------------------------------------------------------------------------
__global__ __launch_bounds__(256) void xproj_kernel(
    const float* __restrict__ X,
    const float* __restrict__ W,
    const float* __restrict__ bias)
{
    __shared__ float Xs[16][128];
    __shared__ float Ws2[16][128];

    const int m0  = blockIdx.y * 128;
    const int n0  = blockIdx.x * 128;
    const int tid = threadIdx.x;
    const int tx  = tid & 15;
    const int ty  = tid >> 4;

    unsigned long long accp[8][4];
#pragma unroll
    for (int i = 0; i < 8; i++)
#pragma unroll
        for (int j = 0; j < 4; j++) accp[i][j] = 0ULL;

    const float* Xg = X + (size_t)m0 * DIM;
    const float* Wg = W + (size_t)n0 * DIM;

    for (int kt = 0; kt < DIM; kt += 16) {
        float4 xa[2], wa[2];
#pragma unroll
        for (int i = 0; i < 2; i++) {
            int idx = tid + i * 256;
            int row = idx >> 2, kq = idx & 3;
            xa[i] = *(const float4*)(Xg + (size_t)row * DIM + kt + kq * 4);
            wa[i] = *(const float4*)(Wg + (size_t)row * DIM + kt + kq * 4);
        }
        __syncthreads();
#pragma unroll
        for (int i = 0; i < 2; i++) {
            int idx = tid + i * 256;
            int row = idx >> 2, kq = idx & 3;
            Xs[kq * 4 + 0][row] = xa[i].x;  Xs[kq * 4 + 1][row] = xa[i].y;
            Xs[kq * 4 + 2][row] = xa[i].z;  Xs[kq * 4 + 3][row] = xa[i].w;
            Ws2[kq * 4 + 0][row] = wa[i].x; Ws2[kq * 4 + 1][row] = wa[i].y;
            Ws2[kq * 4 + 2][row] = wa[i].z; Ws2[kq * 4 + 3][row] = wa[i].w;
        }
        __syncthreads();

#pragma unroll
        for (int k = 0; k < 16; k++) {
            float a[8];
            *(float4*)&a[0] = *(const float4*)&Xs[k][ty * 4];
            *(float4*)&a[4] = *(const float4*)&Xs[k][ty * 4 + 64];
            ulonglong2 b0 = *(const ulonglong2*)&Ws2[k][tx * 4];
            ulonglong2 b1 = *(const ulonglong2*)&Ws2[k][tx * 4 + 64];
#pragma unroll
            for (int i = 0; i < 8; i++) {
                unsigned long long ai = splat2(a[i]);
                ffma2(accp[i][0], ai, b0.x);
                ffma2(accp[i][1], ai, b0.y);
                ffma2(accp[i][2], ai, b1.x);
                ffma2(accp[i][3], ai, b1.y);
            }
        }
    }

    float4 blo = *(const float4*)(bias + n0 + tx * 4);
    float4 bhi = *(const float4*)(bias + n0 + 64 + tx * 4);
#pragma unroll
    for (int i = 0; i < 8; i++) {
        int m = m0 + ty * 4 + ((i < 4) ? i : (64 + i - 4));
        float c[8];
        unpack2(accp[i][0], c[0], c[1]);
        unpack2(accp[i][1], c[2], c[3]);
        unpack2(accp[i][2], c[4], c[5]);
        unpack2(accp[i][3], c[6], c[7]);
        float4 v0, v1;
        v0.x = c[0] + blo.x; v0.y = c[1] + blo.y;
        v0.z = c[2] + blo.z; v0.w = c[3] + blo.w;
        v1.x = c[4] + bhi.x; v1.y = c[5] + bhi.y;
        v1.z = c[6] + bhi.z; v1.w = c[7] + bhi.w;
        *(float4*)&g_xp[(size_t)m * G3 + n0 + tx * 4]      = v0;
        *(float4*)&g_xp[(size_t)m * G3 + n0 + 64 + tx * 4] = v1;
    }
}

// ---------------------------------------------------------------------------
// Kernel 2: persistent GRU scan (R6 structure), flag barrier + cp.async.
// Grid: 128 blocks = 4 batch-groups (bg, 32 batches) x 32 col-groups (cg, 16c).
// Block: 256 threads = 8 warps; warp ks owns k-range [ks*64, +64).
// Lane: bgrp = lane>>2 (batches {bgrp+8i}), cgrp = lane&3 (cols {cgrp+4i}).
// Gate phase: thread tid -> col co=tid>>4, batches {2*(tid&15), +1}.
// ---------------------------------------------------------------------------
__global__ __launch_bounds__(STPB, 1) void scan_kernel(
    const float* __restrict__ Whh,
    const float* __restrict__ bhh,
    float* __restrict__ out)
{
    extern __shared__ float smem[];
    float* wsh = smem;                     // 48 rows x WS
    float* hsh = smem + 48 * WS;           // 32 rows x WS
    float* red = smem + 80 * WS;           // [3][16][8][REDL]

    const int tid  = threadIdx.x;
    const int bk   = blockIdx.x;
    const int bg   = bk >> 5;
    const int cg   = bk & 31;
    const int ks   = tid >> 5;
    const int lane = tid & 31;
    const int bgrp = lane >> 2;
    const int cgrp = lane & 3;
    const int k0   = ks * 64;

    // persistent W rows: smem row (g*16 + lc) <- Whh row (g*512 + cg*16 + lc)
    for (int i = tid; i < 48 * 128; i += STPB) {
        int row = i >> 7, q = i & 127;
        int g = row >> 4, lc = row & 15;
        *(float4*)&wsh[row * WS + q * 4] =
            *(const float4*)(Whh + (size_t)(g * 512 + cg * 16 + lc) * 512 + q * 4);
    }

    // gate-phase mapping
    const int co  = tid >> 4;
    const int bo  = (tid & 15) * 2;
    const int cGo = cg * 16 + co;
    const int bGo = bg * 32 + bo;
    float bh[3];
#pragma unroll
    for (int g = 0; g < 3; g++) bh[g] = bhh[g * 512 + cGo];
    __syncthreads();

    float hprev[2] = {0.f, 0.f};

    // staging map: 16 cp.async per thread, rows j*2+srow, 16B at scol
    const int srow = tid >> 7;
    const int scol = (tid & 127) * 4;
    unsigned int stg_s[16];
#pragma unroll
    for (int j = 0; j < 16; j++)
        stg_s[j] = (unsigned int)__cvta_generic_to_shared(
            &hsh[(j * 2 + srow) * WS + scol]);

    for (int t = 0; t < T_STEPS; t++) {
        // xp gate inputs (issued before the barrier poll -> latency hidden)
        float xgv[2][3];
        {
            const float* xb = g_xp + ((size_t)t * BATCH + bGo) * G3 + cGo;
#pragma unroll
            for (int j = 0; j < 2; j++)
#pragma unroll
                for (int g = 0; g < 3; g++)
                    xgv[j][g] = xb[(size_t)j * G3 + g * 512];
        }

        if (t > 0) {
            // acquire: all 32 group blocks have finished step t-1
            if (tid < 32) {
                volatile unsigned* f = &g_flagv[bg * 32 + tid];
                while (*f < (unsigned)t) { }
            }
            __threadfence();
            __syncthreads();

            // stage 32x512 h slice via cp.async (no register roundtrip)
            const float* hp = out + (size_t)(t - 1) * (BATCH * HID)
                                  + (size_t)(bg * 32) * HID;
#pragma unroll
            for (int j = 0; j < 16; j++)
                cpasync16(stg_s[j], hp + (size_t)(j * 2 + srow) * HID + scol);
            asm volatile("cp.async.commit_group;");
            asm volatile("cp.async.wait_group 0;" ::: "memory");
            __syncthreads();

            unsigned long long acc[4][4][3];
#pragma unroll
            for (int bi = 0; bi < 4; bi++)
#pragma unroll
                for (int ci = 0; ci < 4; ci++)
#pragma unroll
                    for (int g = 0; g < 3; g++) acc[bi][ci][g] = 0ULL;

#pragma unroll 2
            for (int kk = 0; kk < 64; kk += 4) {
                const int k = k0 + kk;
                ulonglong2 h2[4];
#pragma unroll
                for (int bi = 0; bi < 4; bi++)
                    h2[bi] = *(const ulonglong2*)&hsh[(bgrp + 8 * bi) * WS + k];
                ulonglong2 w2[3][4];
#pragma unroll
                for (int g = 0; g < 3; g++)
#pragma unroll
                    for (int ci = 0; ci < 4; ci++)
                        w2[g][ci] = *(const ulonglong2*)
                            &wsh[(g * 16 + cgrp + 4 * ci) * WS + k];
#pragma unroll
                for (int bi = 0; bi < 4; bi++)
#pragma unroll
                    for (int ci = 0; ci < 4; ci++)
#pragma unroll
                        for (int g = 0; g < 3; g++) {
                            ffma2(acc[bi][ci][g], h2[bi].x, w2[g][ci].x);
                            ffma2(acc[bi][ci][g], h2[bi].y, w2[g][ci].y);
                        }
            }

            // publish partials: red[g][c][ks][b]
#pragma unroll
            for (int bi = 0; bi < 4; bi++)
#pragma unroll
                for (int ci = 0; ci < 4; ci++)
#pragma unroll
                    for (int g = 0; g < 3; g++) {
                        float lo, hi;
                        unpack2(acc[bi][ci][g], lo, hi);
                        int b = bgrp + 8 * bi;
                        int c = cgrp + 4 * ci;
                        red[((g * 16 + c) * 8 + ks) * REDL + b] = lo + hi;
                    }
            __syncthreads();
        }

        // gate phase: 2 outputs per thread (col co, batches bo, bo+1)
        {
            float* ob = out + (size_t)t * (BATCH * HID);
#pragma unroll
            for (int j = 0; j < 2; j++) {
                float s[3] = {0.f, 0.f, 0.f};
                if (t > 0) {
#pragma unroll
                    for (int g = 0; g < 3; g++) {
                        float a = 0.f;
#pragma unroll
                        for (int k8 = 0; k8 < 8; k8++)
                            a += red[((g * 16 + co) * 8 + k8) * REDL + bo + j];
                        s[g] = a;
                    }
                }
                float hr = s[0] + bh[0];
                float hz = s[1] + bh[1];
                float hn = s[2] + bh[2];
                float r = 1.f / (1.f + __expf(-(xgv[j][0] + hr)));
                float z = 1.f / (1.f + __expf(-(xgv[j][1] + hz)));
                float n = tanhf(xgv[j][2] + r * hn);
                float hv = (1.f - z) * n + z * hprev[j];
                hprev[j] = hv;
                ob[(size_t)(bGo + j) * HID + cGo] = hv;
            }
        }

        // release: signal step t complete
        if (t < T_STEPS - 1) {
            __threadfence();
            __syncthreads();
            if (tid == 0) g_flagv[bk] = (unsigned)(t + 1);
        }
    }

    // cleanup: reset flags/counters for next graph replay
    __syncthreads();
    if (tid == 0) {
        atomicAdd(&g_cA[bg], 1u);
        while (((volatile unsigned*)g_cA)[bg] < 32u) { }
        g_flagv[bk] = 0u;              // safe: all group blocks past all polls
        __threadfence();
        unsigned q = atomicAdd(&g_cB[bg], 1u);
        if (q == 31u) {                // last block resets counters
            g_cA[bg] = 0u;
            g_cB[bg] = 0u;
            __threadfence();
        }
    }
}

// ---------------------------------------------------------------------------
extern "C" void kernel_launch(void* const* d_in, const int* in_sizes, int n_in,
                              void* d_out, int out_size)
{
    const float* inputs = (const float*)d_in[0];
    const float* W_ih   = (const float*)d_in[1];
    const float* W_hh   = (const float*)d_in[2];
    const float* b_ih   = (const float*)d_in[3];
    const float* b_hh   = (const float*)d_in[4];
    float* out = (float*)d_out;

    (void)in_sizes; (void)n_in; (void)out_size;

    const int dyn_smem =
        (80 * WS + 3 * 16 * 8 * REDL) * (int)sizeof(float);   // ~215 KB
    static int smem_set = 0;
    if (!smem_set) {
        cudaFuncSetAttribute(scan_kernel,
                             cudaFuncAttributeMaxDynamicSharedMemorySize, dyn_smem);
        smem_set = 1;
    }

    dim3 g1(G3 / 128, (T_STEPS * BATCH) / 128, 1);
    xproj_kernel<<<g1, 256>>>(inputs, W_ih, b_ih);
    scan_kernel<<<NB, STPB, dyn_smem>>>(W_hh, b_hh, out);
}

// round 9
// speedup vs baseline: 1.3050x; 1.0745x over previous
#include <cuda_runtime.h>
#include <math.h>

#define T_STEPS 512
#define BATCH   128
#define DIM     512
#define HID     512
#define G3      1536

#define NB   128      // scan blocks: 4 batch-groups x 32 col-groups
#define STPB 256
#define WS   516      // padded smem row stride (floats)
#define REDL 33       // reduction inner stride

__device__ float g_xp[(size_t)T_STEPS * BATCH * G3];
__device__ unsigned int g_bar[4 * T_STEPS];

__device__ __forceinline__ void ffma2(unsigned long long& d,
                                      unsigned long long a,
                                      unsigned long long b) {
    asm("fma.rn.f32x2 %0, %1, %2, %0;" : "+l"(d) : "l"(a), "l"(b));
}
__device__ __forceinline__ void unpack2(unsigned long long v, float& lo, float& hi) {
    asm("mov.b64 {%0, %1}, %2;" : "=f"(lo), "=f"(hi) : "l"(v));
}
__device__ __forceinline__ unsigned tf32r(float x) {
    unsigned r; asm("cvt.rna.tf32.f32 %0, %1;" : "=r"(r) : "f"(x)); return r;
}
__device__ __forceinline__ void mma_tf32(float c[4],
    unsigned a0, unsigned a1, unsigned a2, unsigned a3,
    unsigned b0, unsigned b1) {
    asm volatile(
        "mma.sync.aligned.m16n8k8.row.col.f32.tf32.tf32.f32 "
        "{%0,%1,%2,%3}, {%4,%5,%6,%7}, {%8,%9}, {%0,%1,%2,%3};"
        : "+f"(c[0]), "+f"(c[1]), "+f"(c[2]), "+f"(c[3])
        : "r"(a0), "r"(a1), "r"(a2), "r"(a3), "r"(b0), "r"(b1));
}

// ---------------------------------------------------------------------------
// Kernel 1: x_proj = X @ W_ih^T + b_ih via tf32 split MMA (fp32-accurate).
// BM=128, BN=64, BK=16. 256 thr = 8 warps (wm = wid&3 -> 32 rows,
// wn = wid>>2 -> 32 cols). Warp: 2 m16-tiles x 4 n8-tiles.
// hi/lo tf32 tiles built once at staging.
// ---------------------------------------------------------------------------
#define XP  18   // smem pad stride
__global__ __launch_bounds__(256) void xproj_kernel(
    const float* __restrict__ X,
    const float* __restrict__ W,
    const float* __restrict__ bias)
{
    __shared__ float Xhi[128][XP], Xlo[128][XP];
    __shared__ float Whi[64][XP],  Wlo[64][XP];

    const int tid  = threadIdx.x;
    const int m0   = blockIdx.y * 128;
    const int n0   = blockIdx.x * 64;
    const int wid  = tid >> 5;
    const int lane = tid & 31;
    const int wm   = wid & 3;
    const int wn   = wid >> 2;
    const int gid  = lane >> 2;
    const int tg   = lane & 3;

    float acc[2][4][4];
#pragma unroll
    for (int mt = 0; mt < 2; mt++)
#pragma unroll
        for (int nt = 0; nt < 4; nt++)
#pragma unroll
            for (int i = 0; i < 4; i++) acc[mt][nt][i] = 0.f;

    // staging map: X 512 float4 (2/thread), W 256 float4 (1/thread)
    const int xr0 = tid >> 2,            xq = (tid & 3) * 4;
    const int xr1 = (tid + 256) >> 2;
    const int wr  = tid >> 2;

    const float* Xg = X + (size_t)m0 * DIM;
    const float* Wg = W + (size_t)n0 * DIM;

    float4 px0 = *(const float4*)(Xg + (size_t)xr0 * DIM + xq);
    float4 px1 = *(const float4*)(Xg + (size_t)xr1 * DIM + xq);
    float4 pw  = *(const float4*)(Wg + (size_t)wr  * DIM + xq);

    for (int kt = 0; kt < DIM; kt += 16) {
        __syncthreads();   // previous tile fully consumed
        // convert staged regs -> hi/lo smem tiles
        {
            float v[4], hi, lo;
            float* xh0 = &Xhi[xr0][xq]; float* xl0 = &Xlo[xr0][xq];
            v[0]=px0.x; v[1]=px0.y; v[2]=px0.z; v[3]=px0.w;
#pragma unroll
            for (int i = 0; i < 4; i++) {
                hi = __uint_as_float(tf32r(v[i])); lo = v[i] - hi;
                xh0[i] = hi; xl0[i] = __uint_as_float(tf32r(lo));
            }
            float* xh1 = &Xhi[xr1][xq]; float* xl1 = &Xlo[xr1][xq];
            v[0]=px1.x; v[1]=px1.y; v[2]=px1.z; v[3]=px1.w;
#pragma unroll
            for (int i = 0; i < 4; i++) {
                hi = __uint_as_float(tf32r(v[i])); lo = v[i] - hi;
                xh1[i] = hi; xl1[i] = __uint_as_float(tf32r(lo));
            }
            float* wh = &Whi[wr][xq]; float* wl = &Wlo[wr][xq];
            v[0]=pw.x; v[1]=pw.y; v[2]=pw.z; v[3]=pw.w;
#pragma unroll
            for (int i = 0; i < 4; i++) {
                hi = __uint_as_float(tf32r(v[i])); lo = v[i] - hi;
                wh[i] = hi; wl[i] = __uint_as_float(tf32r(lo));
            }
        }
        // prefetch next tile while this one computes
        if (kt + 16 < DIM) {
            px0 = *(const float4*)(Xg + (size_t)xr0 * DIM + kt + 16 + xq);
            px1 = *(const float4*)(Xg + (size_t)xr1 * DIM + kt + 16 + xq);
            pw  = *(const float4*)(Wg + (size_t)wr  * DIM + kt + 16 + xq);
        }
        __syncthreads();

#pragma unroll
        for (int kb = 0; kb < 16; kb += 8) {
            unsigned ahi[2][4], alo[2][4], bhi[4][2], blo[4][2];
#pragma unroll
            for (int mt = 0; mt < 2; mt++) {
                int r0 = wm * 32 + mt * 16 + gid;
                ahi[mt][0] = __float_as_uint(Xhi[r0    ][kb + tg]);
                ahi[mt][1] = __float_as_uint(Xhi[r0 + 8][kb + tg]);
                ahi[mt][2] = __float_as_uint(Xhi[r0    ][kb + tg + 4]);
                ahi[mt][3] = __float_as_uint(Xhi[r0 + 8][kb + tg + 4]);
                alo[mt][0] = __float_as_uint(Xlo[r0    ][kb + tg]);
                alo[mt][1] = __float_as_uint(Xlo[r0 + 8][kb + tg]);
                alo[mt][2] = __float_as_uint(Xlo[r0    ][kb + tg + 4]);
                alo[mt][3] = __float_as_uint(Xlo[r0 + 8][kb + tg + 4]);
            }
#pragma unroll
            for (int nt = 0; nt < 4; nt++) {
                int nr = wn * 32 + nt * 8 + gid;
                bhi[nt][0] = __float_as_uint(Whi[nr][kb + tg]);
                bhi[nt][1] = __float_as_uint(Whi[nr][kb + tg + 4]);
                blo[nt][0] = __float_as_uint(Wlo[nr][kb + tg]);
                blo[nt][1] = __float_as_uint(Wlo[nr][kb + tg + 4]);
            }
#pragma unroll
            for (int mt = 0; mt < 2; mt++)
#pragma unroll
                for (int nt = 0; nt < 4; nt++) {
                    mma_tf32(acc[mt][nt], ahi[mt][0], ahi[mt][1], ahi[mt][2],
                             ahi[mt][3], bhi[nt][0], bhi[nt][1]);
                    mma_tf32(acc[mt][nt], ahi[mt][0], ahi[mt][1], ahi[mt][2],
                             ahi[mt][3], blo[nt][0], blo[nt][1]);
                    mma_tf32(acc[mt][nt], alo[mt][0], alo[mt][1], alo[mt][2],
                             alo[mt][3], bhi[nt][0], bhi[nt][1]);
                }
        }
    }

    // epilogue: + bias, float2 stores (c0,c1) and (c2,c3)
#pragma unroll
    for (int nt = 0; nt < 4; nt++) {
        int nb = n0 + wn * 32 + nt * 8 + 2 * tg;
        float2 bs = *(const float2*)(bias + nb);
#pragma unroll
        for (int mt = 0; mt < 2; mt++) {
            int r0 = m0 + wm * 32 + mt * 16 + gid;
            float2 v0, v1;
            v0.x = acc[mt][nt][0] + bs.x; v0.y = acc[mt][nt][1] + bs.y;
            v1.x = acc[mt][nt][2] + bs.x; v1.y = acc[mt][nt][3] + bs.y;
            *(float2*)&g_xp[(size_t)r0 * G3 + nb]       = v0;
            *(float2*)&g_xp[(size_t)(r0 + 8) * G3 + nb] = v1;
        }
    }
}

// ---------------------------------------------------------------------------
// Kernel 2: persistent GRU scan — exact R6 champion version.
// ---------------------------------------------------------------------------
__global__ __launch_bounds__(STPB, 1) void scan_kernel(
    const float* __restrict__ Whh,
    const float* __restrict__ bhh,
    float* __restrict__ out)
{
    extern __shared__ float smem[];
    float* wsh = smem;                     // 48 rows x WS
    float* hsh = smem + 48 * WS;           // 32 rows x WS
    float* red = smem + 80 * WS;           // [3][16][8][REDL]

    const int tid  = threadIdx.x;
    const int bk   = blockIdx.x;
    const int bg   = bk >> 5;
    const int cg   = bk & 31;
    const int ks   = tid >> 5;
    const int lane = tid & 31;
    const int bgrp = lane >> 2;
    const int cgrp = lane & 3;
    const int k0   = ks * 64;

    for (int i = tid; i < 48 * 128; i += STPB) {
        int row = i >> 7, q = i & 127;
        int g = row >> 4, lc = row & 15;
        *(float4*)&wsh[row * WS + q * 4] =
            *(const float4*)(Whh + (size_t)(g * 512 + cg * 16 + lc) * 512 + q * 4);
    }

    const int co  = tid >> 4;
    const int bo  = (tid & 15) * 2;
    const int cGo = cg * 16 + co;
    const int bGo = bg * 32 + bo;
    float bh[3];
#pragma unroll
    for (int g = 0; g < 3; g++) bh[g] = bhh[g * 512 + cGo];
    __syncthreads();

    float hprev[2] = {0.f, 0.f};

    const int srow = tid >> 7;
    const int scol = (tid & 127) * 4;

    for (int t = 0; t < T_STEPS; t++) {
        float xgv[2][3];
        {
            const float* xb = g_xp + ((size_t)t * BATCH + bGo) * G3 + cGo;
#pragma unroll
            for (int j = 0; j < 2; j++)
#pragma unroll
                for (int g = 0; g < 3; g++)
                    xgv[j][g] = xb[(size_t)j * G3 + g * 512];
        }

        if (t > 0) {
            const float* hp = out + (size_t)(t - 1) * (BATCH * HID)
                                  + (size_t)(bg * 32) * HID;
#pragma unroll
            for (int j = 0; j < 16; j++) {
                int row = j * 2 + srow;
                *(float4*)&hsh[row * WS + scol] =
                    *(const float4*)(hp + (size_t)row * HID + scol);
            }
            __syncthreads();

            unsigned long long acc[4][4][3];
#pragma unroll
            for (int bi = 0; bi < 4; bi++)
#pragma unroll
                for (int ci = 0; ci < 4; ci++)
#pragma unroll
                    for (int g = 0; g < 3; g++) acc[bi][ci][g] = 0ULL;

#pragma unroll 2
            for (int kk = 0; kk < 64; kk += 4) {
                const int k = k0 + kk;
                ulonglong2 h2[4];
#pragma unroll
                for (int bi = 0; bi < 4; bi++)
                    h2[bi] = *(const ulonglong2*)&hsh[(bgrp + 8 * bi) * WS + k];
                ulonglong2 w2[3][4];
#pragma unroll
                for (int g = 0; g < 3; g++)
#pragma unroll
                    for (int ci = 0; ci < 4; ci++)
                        w2[g][ci] = *(const ulonglong2*)
                            &wsh[(g * 16 + cgrp + 4 * ci) * WS + k];
#pragma unroll
                for (int bi = 0; bi < 4; bi++)
#pragma unroll
                    for (int ci = 0; ci < 4; ci++)
#pragma unroll
                        for (int g = 0; g < 3; g++) {
                            ffma2(acc[bi][ci][g], h2[bi].x, w2[g][ci].x);
                            ffma2(acc[bi][ci][g], h2[bi].y, w2[g][ci].y);
                        }
            }

#pragma unroll
            for (int bi = 0; bi < 4; bi++)
#pragma unroll
                for (int ci = 0; ci < 4; ci++)
#pragma unroll
                    for (int g = 0; g < 3; g++) {
                        float lo, hi;
                        unpack2(acc[bi][ci][g], lo, hi);
                        int b = bgrp + 8 * bi;
                        int c = cgrp + 4 * ci;
                        red[((g * 16 + c) * 8 + ks) * REDL + b] = lo + hi;
                    }
            __syncthreads();
        }

        {
            float* ob = out + (size_t)t * (BATCH * HID);
#pragma unroll
            for (int j = 0; j < 2; j++) {
                float s[3] = {0.f, 0.f, 0.f};
                if (t > 0) {
#pragma unroll
                    for (int g = 0; g < 3; g++) {
                        float a = 0.f;
#pragma unroll
                        for (int k8 = 0; k8 < 8; k8++)
                            a += red[((g * 16 + co) * 8 + k8) * REDL + bo + j];
                        s[g] = a;
                    }
                }
                float hr = s[0] + bh[0];
                float hz = s[1] + bh[1];
                float hn = s[2] + bh[2];
                float r = 1.f / (1.f + __expf(-(xgv[j][0] + hr)));
                float z = 1.f / (1.f + __expf(-(xgv[j][1] + hz)));
                float n = tanhf(xgv[j][2] + r * hn);
                float hv = (1.f - z) * n + z * hprev[j];
                hprev[j] = hv;
                ob[(size_t)(bGo + j) * HID + cGo] = hv;
            }
        }

        if (t < T_STEPS - 1) {
            __threadfence();
            __syncthreads();
            if (tid == 0) {
                unsigned* ctr = &g_bar[bg * T_STEPS + t];
                unsigned prev = atomicAdd(ctr, 1u);
                if (prev + 1u < 32u) {
                    while (*((volatile unsigned*)ctr) < 32u) { }
                }
                if (cg == 0 && t > 0) g_bar[bg * T_STEPS + t - 1] = 0u;
                __threadfence();
            }
            __syncthreads();
        }
    }

    __syncthreads();
    if (tid == 0) {
        __threadfence();
        unsigned d = atomicAdd(&g_bar[bg * T_STEPS + T_STEPS - 1], 1u);
        if (d + 1u == 32u) {
            g_bar[bg * T_STEPS + T_STEPS - 2] = 0u;
            g_bar[bg * T_STEPS + T_STEPS - 1] = 0u;
            __threadfence();
        }
    }
}

// ---------------------------------------------------------------------------
extern "C" void kernel_launch(void* const* d_in, const int* in_sizes, int n_in,
                              void* d_out, int out_size)
{
    const float* inputs = (const float*)d_in[0];
    const float* W_ih   = (const float*)d_in[1];
    const float* W_hh   = (const float*)d_in[2];
    const float* b_ih   = (const float*)d_in[3];
    const float* b_hh   = (const float*)d_in[4];
    float* out = (float*)d_out;

    (void)in_sizes; (void)n_in; (void)out_size;

    const int dyn_smem =
        (80 * WS + 3 * 16 * 8 * REDL) * (int)sizeof(float);   // ~211 KB
    static int smem_set = 0;
    if (!smem_set) {
        cudaFuncSetAttribute(scan_kernel,
                             cudaFuncAttributeMaxDynamicSharedMemorySize, dyn_smem);
        smem_set = 1;
    }

    dim3 g1(G3 / 64, (T_STEPS * BATCH) / 128, 1);   // 24 x 512
    xproj_kernel<<<g1, 256>>>(inputs, W_ih, b_ih);
    scan_kernel<<<NB, STPB, dyn_smem>>>(W_hh, b_hh, out);
}

// round 10
// speedup vs baseline: 1.4842x; 1.1373x over previous
#include <cuda_runtime.h>
#include <math.h>

#define T_STEPS 512
#define BATCH   128
#define DIM     512
#define HID     512
#define G3      1536
#define MROWS   (T_STEPS * BATCH)     // 65536

#define NB   128
#define STPB 256
#define WS   516
#define REDL 33
#define SP   20                       // xproj smem row stride (floats)

__device__ float g_xp[(size_t)T_STEPS * BATCH * G3];
__device__ float g_xhi[(size_t)MROWS * DIM];
__device__ float g_xlo[(size_t)MROWS * DIM];
__device__ float g_whi[G3 * DIM];
__device__ float g_wlo[G3 * DIM];
__device__ unsigned int g_bar[4 * T_STEPS];

__device__ __forceinline__ void ffma2(unsigned long long& d,
                                      unsigned long long a,
                                      unsigned long long b) {
    asm("fma.rn.f32x2 %0, %1, %2, %0;" : "+l"(d) : "l"(a), "l"(b));
}
__device__ __forceinline__ void unpack2(unsigned long long v, float& lo, float& hi) {
    asm("mov.b64 {%0, %1}, %2;" : "=f"(lo), "=f"(hi) : "l"(v));
}
__device__ __forceinline__ float tf32f(float x) {
    unsigned r; asm("cvt.rna.tf32.f32 %0, %1;" : "=r"(r) : "f"(x));
    return __uint_as_float(r);
}
__device__ __forceinline__ void mma_tf32(float c[4],
    unsigned a0, unsigned a1, unsigned a2, unsigned a3,
    unsigned b0, unsigned b1) {
    asm volatile(
        "mma.sync.aligned.m16n8k8.row.col.f32.tf32.tf32.f32 "
        "{%0,%1,%2,%3}, {%4,%5,%6,%7}, {%8,%9}, {%0,%1,%2,%3};"
        : "+f"(c[0]), "+f"(c[1]), "+f"(c[2]), "+f"(c[3])
        : "r"(a0), "r"(a1), "r"(a2), "r"(a3), "r"(b0), "r"(b1));
}
__device__ __forceinline__ void cpasync16(unsigned int saddr, const void* gaddr) {
    asm volatile("cp.async.cg.shared.global [%0], [%1], 16;"
                 :: "r"(saddr), "l"(gaddr));
}

// ---------------------------------------------------------------------------
// Prep: hi/lo tf32 split, stored fragment-permuted within each 16-k window:
//   value at local k = 4q+i  ->  position i*4+q
// ---------------------------------------------------------------------------
__global__ __launch_bounds__(256) void cvt_kernel(
    const float* __restrict__ src, float* __restrict__ dhi,
    float* __restrict__ dlo, int nrows)
{
    size_t idx = (size_t)blockIdx.x * 256 + threadIdx.x;   // one float4
    if (idx >= (size_t)nrows * (DIM / 4)) return;
    size_t m = idx >> 7;
    int f = (int)(idx & 127);
    int kt = f >> 2, q = f & 3;
    float4 v = ((const float4*)src)[idx];
    float vv[4] = {v.x, v.y, v.z, v.w};
    size_t base = m * DIM + kt * 16 + q;
#pragma unroll
    for (int i = 0; i < 4; i++) {
        float hi = tf32f(vv[i]);
        dhi[base + i * 4] = hi;
        dlo[base + i * 4] = tf32f(vv[i] - hi);
    }
}

// ---------------------------------------------------------------------------
// Kernel 1: x_proj via 3-term tf32 MMA. BM=128, BN=128, BK=16.
// 8 warps = 4 wm x 2 wn; warp tile m32 x n64 (2 m16 x 8 n8).
// A frags direct from permuted global; B via cp.async -> smem.
// ---------------------------------------------------------------------------
__global__ __launch_bounds__(256, 2) void xproj_kernel(const float* __restrict__ bias)
{
    __shared__ float Whi_s[128 * SP];
    __shared__ float Wlo_s[128 * SP];

    const int tid  = threadIdx.x;
    const int m0   = blockIdx.y * 128;
    const int n0   = blockIdx.x * 128;
    const int wid  = tid >> 5;
    const int lane = tid & 31;
    const int wm   = wid & 3;
    const int wn   = wid >> 2;
    const int gid  = lane >> 2;
    const int tg   = lane & 3;

    float acc[2][8][4];
#pragma unroll
    for (int mt = 0; mt < 2; mt++)
#pragma unroll
        for (int nt = 0; nt < 8; nt++)
#pragma unroll
            for (int i = 0; i < 4; i++) acc[mt][nt][i] = 0.f;

    // W staging map: thread fills rows sr and sr+64, f4 col sj
    const int sr = tid >> 2, sj = tid & 3;
    const size_t wg0 = (size_t)(n0 + sr) * DIM + 4 * sj;
    const size_t wg1 = (size_t)(n0 + 64 + sr) * DIM + 4 * sj;
    const unsigned dh0 = (unsigned)__cvta_generic_to_shared(&Whi_s[sr * SP + 4 * sj]);
    const unsigned dh1 = (unsigned)__cvta_generic_to_shared(&Whi_s[(64 + sr) * SP + 4 * sj]);
    const unsigned dl0 = (unsigned)__cvta_generic_to_shared(&Wlo_s[sr * SP + 4 * sj]);
    const unsigned dl1 = (unsigned)__cvta_generic_to_shared(&Wlo_s[(64 + sr) * SP + 4 * sj]);

    const size_t ar0 = (size_t)(m0 + wm * 32 + gid) * DIM + 4 * tg;        // mt=0 row
    const size_t ar8 = ar0 + 8 * DIM;

    for (int kt = 0; kt < DIM; kt += 16) {
        // fill W smem (pure copy; data pre-converted & permuted)
        cpasync16(dh0, g_whi + wg0 + kt);
        cpasync16(dh1, g_whi + wg1 + kt);
        cpasync16(dl0, g_wlo + wg0 + kt);
        cpasync16(dl1, g_wlo + wg1 + kt);
        asm volatile("cp.async.commit_group;");

        // A fragments direct from global (issued while cp.async in flight)
        uint4 ahi0[2], ahi1[2], alo0[2], alo1[2];
#pragma unroll
        for (int mt = 0; mt < 2; mt++) {
            size_t r0 = ar0 + (size_t)(mt * 16) * DIM + kt;
            size_t r8 = ar8 + (size_t)(mt * 16) * DIM + kt;
            ahi0[mt] = *(const uint4*)(g_xhi + r0);
            ahi1[mt] = *(const uint4*)(g_xhi + r8);
            alo0[mt] = *(const uint4*)(g_xlo + r0);
            alo1[mt] = *(const uint4*)(g_xlo + r8);
        }

        asm volatile("cp.async.wait_group 0;" ::: "memory");
        __syncthreads();

#pragma unroll
        for (int nt = 0; nt < 8; nt++) {
            int nr = wn * 64 + nt * 8 + gid;
            uint4 bh = *(const uint4*)&Whi_s[nr * SP + 4 * tg];
            uint4 bl = *(const uint4*)&Wlo_s[nr * SP + 4 * tg];
#pragma unroll
            for (int mt = 0; mt < 2; mt++) {
                // kb = 0 half
                mma_tf32(acc[mt][nt], ahi0[mt].x, ahi1[mt].x, ahi0[mt].y,
                         ahi1[mt].y, bh.x, bh.y);
                mma_tf32(acc[mt][nt], ahi0[mt].x, ahi1[mt].x, ahi0[mt].y,
                         ahi1[mt].y, bl.x, bl.y);
                mma_tf32(acc[mt][nt], alo0[mt].x, alo1[mt].x, alo0[mt].y,
                         alo1[mt].y, bh.x, bh.y);
                // kb = 8 half
                mma_tf32(acc[mt][nt], ahi0[mt].z, ahi1[mt].z, ahi0[mt].w,
                         ahi1[mt].w, bh.z, bh.w);
                mma_tf32(acc[mt][nt], ahi0[mt].z, ahi1[mt].z, ahi0[mt].w,
                         ahi1[mt].w, bl.z, bl.w);
                mma_tf32(acc[mt][nt], alo0[mt].z, alo1[mt].z, alo0[mt].w,
                         alo1[mt].w, bh.z, bh.w);
            }
        }
        __syncthreads();   // W smem consumed; safe to refill
    }

    // epilogue: + bias (fragment mapping verified in R9)
#pragma unroll
    for (int nt = 0; nt < 8; nt++) {
        int nb = n0 + wn * 64 + nt * 8 + 2 * tg;
        float2 bs = *(const float2*)(bias + nb);
#pragma unroll
        for (int mt = 0; mt < 2; mt++) {
            int r0 = m0 + wm * 32 + mt * 16 + gid;
            float2 v0, v1;
            v0.x = acc[mt][nt][0] + bs.x; v0.y = acc[mt][nt][1] + bs.y;
            v1.x = acc[mt][nt][2] + bs.x; v1.y = acc[mt][nt][3] + bs.y;
            *(float2*)&g_xp[(size_t)r0 * G3 + nb]       = v0;
            *(float2*)&g_xp[(size_t)(r0 + 8) * G3 + nb] = v1;
        }
    }
}

// ---------------------------------------------------------------------------
// Kernel 2: persistent GRU scan — exact R6 champion version.
// ---------------------------------------------------------------------------
__global__ __launch_bounds__(STPB, 1) void scan_kernel(
    const float* __restrict__ Whh,
    const float* __restrict__ bhh,
    float* __restrict__ out)
{
    extern __shared__ float smem[];
    float* wsh = smem;
    float* hsh = smem + 48 * WS;
    float* red = smem + 80 * WS;

    const int tid  = threadIdx.x;
    const int bk   = blockIdx.x;
    const int bg   = bk >> 5;
    const int cg   = bk & 31;
    const int ks   = tid >> 5;
    const int lane = tid & 31;
    const int bgrp = lane >> 2;
    const int cgrp = lane & 3;
    const int k0   = ks * 64;

    for (int i = tid; i < 48 * 128; i += STPB) {
        int row = i >> 7, q = i & 127;
        int g = row >> 4, lc = row & 15;
        *(float4*)&wsh[row * WS + q * 4] =
            *(const float4*)(Whh + (size_t)(g * 512 + cg * 16 + lc) * 512 + q * 4);
    }

    const int co  = tid >> 4;
    const int bo  = (tid & 15) * 2;
    const int cGo = cg * 16 + co;
    const int bGo = bg * 32 + bo;
    float bh[3];
#pragma unroll
    for (int g = 0; g < 3; g++) bh[g] = bhh[g * 512 + cGo];
    __syncthreads();

    float hprev[2] = {0.f, 0.f};
    const int srow = tid >> 7;
    const int scol = (tid & 127) * 4;

    for (int t = 0; t < T_STEPS; t++) {
        float xgv[2][3];
        {
            const float* xb = g_xp + ((size_t)t * BATCH + bGo) * G3 + cGo;
#pragma unroll
            for (int j = 0; j < 2; j++)
#pragma unroll
                for (int g = 0; g < 3; g++)
                    xgv[j][g] = xb[(size_t)j * G3 + g * 512];
        }

        if (t > 0) {
            const float* hp = out + (size_t)(t - 1) * (BATCH * HID)
                                  + (size_t)(bg * 32) * HID;
#pragma unroll
            for (int j = 0; j < 16; j++) {
                int row = j * 2 + srow;
                *(float4*)&hsh[row * WS + scol] =
                    *(const float4*)(hp + (size_t)row * HID + scol);
            }
            __syncthreads();

            unsigned long long acc[4][4][3];
#pragma unroll
            for (int bi = 0; bi < 4; bi++)
#pragma unroll
                for (int ci = 0; ci < 4; ci++)
#pragma unroll
                    for (int g = 0; g < 3; g++) acc[bi][ci][g] = 0ULL;

#pragma unroll 2
            for (int kk = 0; kk < 64; kk += 4) {
                const int k = k0 + kk;
                ulonglong2 h2[4];
#pragma unroll
                for (int bi = 0; bi < 4; bi++)
                    h2[bi] = *(const ulonglong2*)&hsh[(bgrp + 8 * bi) * WS + k];
                ulonglong2 w2[3][4];
#pragma unroll
                for (int g = 0; g < 3; g++)
#pragma unroll
                    for (int ci = 0; ci < 4; ci++)
                        w2[g][ci] = *(const ulonglong2*)
                            &wsh[(g * 16 + cgrp + 4 * ci) * WS + k];
#pragma unroll
                for (int bi = 0; bi < 4; bi++)
#pragma unroll
                    for (int ci = 0; ci < 4; ci++)
#pragma unroll
                        for (int g = 0; g < 3; g++) {
                            ffma2(acc[bi][ci][g], h2[bi].x, w2[g][ci].x);
                            ffma2(acc[bi][ci][g], h2[bi].y, w2[g][ci].y);
                        }
            }

#pragma unroll
            for (int bi = 0; bi < 4; bi++)
#pragma unroll
                for (int ci = 0; ci < 4; ci++)
#pragma unroll
                    for (int g = 0; g < 3; g++) {
                        float lo, hi;
                        unpack2(acc[bi][ci][g], lo, hi);
                        int b = bgrp + 8 * bi;
                        int c = cgrp + 4 * ci;
                        red[((g * 16 + c) * 8 + ks) * REDL + b] = lo + hi;
                    }
            __syncthreads();
        }

        {
            float* ob = out + (size_t)t * (BATCH * HID);
#pragma unroll
            for (int j = 0; j < 2; j++) {
                float s[3] = {0.f, 0.f, 0.f};
                if (t > 0) {
#pragma unroll
                    for (int g = 0; g < 3; g++) {
                        float a = 0.f;
#pragma unroll
                        for (int k8 = 0; k8 < 8; k8++)
                            a += red[((g * 16 + co) * 8 + k8) * REDL + bo + j];
                        s[g] = a;
                    }
                }
                float hr = s[0] + bh[0];
                float hz = s[1] + bh[1];
                float hn = s[2] + bh[2];
                float r = 1.f / (1.f + __expf(-(xgv[j][0] + hr)));
                float z = 1.f / (1.f + __expf(-(xgv[j][1] + hz)));
                float n = tanhf(xgv[j][2] + r * hn);
                float hv = (1.f - z) * n + z * hprev[j];
                hprev[j] = hv;
                ob[(size_t)(bGo + j) * HID + cGo] = hv;
            }
        }

        if (t < T_STEPS - 1) {
            __threadfence();
            __syncthreads();
            if (tid == 0) {
                unsigned* ctr = &g_bar[bg * T_STEPS + t];
                unsigned prev = atomicAdd(ctr, 1u);
                if (prev + 1u < 32u) {
                    while (*((volatile unsigned*)ctr) < 32u) { }
                }
                if (cg == 0 && t > 0) g_bar[bg * T_STEPS + t - 1] = 0u;
                __threadfence();
            }
            __syncthreads();
        }
    }

    __syncthreads();
    if (tid == 0) {
        __threadfence();
        unsigned d = atomicAdd(&g_bar[bg * T_STEPS + T_STEPS - 1], 1u);
        if (d + 1u == 32u) {
            g_bar[bg * T_STEPS + T_STEPS - 2] = 0u;
            g_bar[bg * T_STEPS + T_STEPS - 1] = 0u;
            __threadfence();
        }
    }
}

// ---------------------------------------------------------------------------
extern "C" void kernel_launch(void* const* d_in, const int* in_sizes, int n_in,
                              void* d_out, int out_size)
{
    const float* inputs = (const float*)d_in[0];
    const float* W_ih   = (const float*)d_in[1];
    const float* W_hh   = (const float*)d_in[2];
    const float* b_ih   = (const float*)d_in[3];
    const float* b_hh   = (const float*)d_in[4];
    float* out = (float*)d_out;

    (void)in_sizes; (void)n_in; (void)out_size;

    const int dyn_smem =
        (80 * WS + 3 * 16 * 8 * REDL) * (int)sizeof(float);
    static int smem_set = 0;
    float* xhi_p; float* xlo_p; float* whi_p; float* wlo_p;
    cudaGetSymbolAddress((void**)&xhi_p, g_xhi);
    cudaGetSymbolAddress((void**)&xlo_p, g_xlo);
    cudaGetSymbolAddress((void**)&whi_p, g_whi);
    cudaGetSymbolAddress((void**)&wlo_p, g_wlo);
    if (!smem_set) {
        cudaFuncSetAttribute(scan_kernel,
                             cudaFuncAttributeMaxDynamicSharedMemorySize, dyn_smem);
        smem_set = 1;
    }

    // prep: hi/lo tf32 split, fragment-permuted
    cvt_kernel<<<(MROWS * (DIM / 4) + 255) / 256, 256>>>(inputs, xhi_p, xlo_p, MROWS);
    cvt_kernel<<<(G3 * (DIM / 4) + 255) / 256, 256>>>(W_ih, whi_p, wlo_p, G3);

    dim3 g1(G3 / 128, MROWS / 128, 1);   // 12 x 512
    xproj_kernel<<<g1, 256>>>(b_ih);
    scan_kernel<<<NB, STPB, dyn_smem>>>(W_hh, b_hh, out);
}